// round 2
// baseline (speedup 1.0000x reference)
#include <cuda_runtime.h>

// Problem constants
#define Bn     1024
#define Kc     1056
#define Nc     2112
#define Mc     1056
#define DVc    5
#define Ec     6336
#define NSYMc  528
#define NITERc 20

#define Tthr   352           // threads per block
#define CPT    3             // checks per thread: Mc / Tthr == 3

// XLA EmitTanh (f32): Eigen-style rational approx, unfused arithmetic.
__device__ __forceinline__ float xla_tanh(float x) {
    const float kClamp = 7.99881172180175781f;
    float ax = fabsf(x);
    float xc = fminf(fmaxf(x, -kClamp), kClamp);
    float x2 = __fmul_rn(xc, xc);
    float p = -2.76076847742355e-16f;
    p = __fadd_rn(__fmul_rn(p, x2), 2.00018790482477e-13f);
    p = __fadd_rn(__fmul_rn(p, x2), -8.60467152213735e-11f);
    p = __fadd_rn(__fmul_rn(p, x2), 5.12229709037114e-08f);
    p = __fadd_rn(__fmul_rn(p, x2), 1.48572235717979e-05f);
    p = __fadd_rn(__fmul_rn(p, x2), 6.37261928875436e-04f);
    p = __fadd_rn(__fmul_rn(p, x2), 4.89352455891786e-03f);
    p = __fmul_rn(p, xc);
    float q = 1.19825839466702e-06f;
    q = __fadd_rn(__fmul_rn(q, x2), 1.18534705686654e-04f);
    q = __fadd_rn(__fmul_rn(q, x2), 2.26843463243900e-03f);
    q = __fadd_rn(__fmul_rn(q, x2), 4.89352518554385e-03f);
    float r = __fdiv_rn(p, q);
    return (ax < 0.0004f) ? x : r;
}

__global__ void __launch_bounds__(Tthr)
simplelink_kernel(const int* __restrict__ bits,
                  const int* __restrict__ a_idx,
                  const float* __restrict__ points_re,
                  const float* __restrict__ points_im,
                  const float* __restrict__ noise_re,
                  const float* __restrict__ noise_im,
                  const float* __restrict__ ebno,
                  float* __restrict__ out)
{
    __shared__ float llr_s[Nc];
    __shared__ float vac_s[Nc];
    __shared__ int   cw_s[Nc];
    __shared__ float pre_s[16], pim_s[16];

    const int b   = blockIdx.x;
    const int tid = threadIdx.x;

    if (tid < 16) { pre_s[tid] = points_re[tid]; pim_s[tid] = points_im[tid]; }

    // ---- load info bits ----
    for (int i = tid; i < Kc; i += Tthr) cw_s[i] = bits[b * Kc + i];
    __syncthreads();

    // ---- LDPC encode: parity_m = XOR of DV info bits ----
    for (int m = tid; m < Mc; m += Tthr) {
        int p = 0;
        #pragma unroll
        for (int j = 0; j < DVc; j++) p += cw_s[a_idx[m * DVc + j]];
        cw_s[Kc + m] = p & 1;
    }
    __syncthreads();

    // ---- noise scaling (replicates reference fp32 scalar chain) ----
    const float eb    = ebno[0];
    const float no    = __fdiv_rn(1.0f,
                         __fmul_rn(__fmul_rn(powf(10.0f, __fdiv_rn(eb, 10.0f)), 0.5f), 4.0f));
    const float sigma = sqrtf(__fdiv_rn(no, 2.0f));

    // ---- QAM map + AWGN + APP demap -> llr ----
    for (int s = tid; s < NSYMc; s += Tthr) {
        int sym = (cw_s[4*s] << 3) | (cw_s[4*s+1] << 2) | (cw_s[4*s+2] << 1) | cw_s[4*s+3];
        float yre = __fadd_rn(pre_s[sym], __fmul_rn(sigma, noise_re[b * NSYMc + s]));
        float yim = __fadd_rn(pim_s[sym], __fmul_rn(sigma, noise_im[b * NSYMc + s]));
        float lg[16];
        #pragma unroll
        for (int i = 0; i < 16; i++) {
            float dr = __fsub_rn(yre, pre_s[i]);
            float di = __fsub_rn(yim, pim_s[i]);
            float d2 = __fadd_rn(__fmul_rn(dr, dr), __fmul_rn(di, di));
            lg[i] = __fdiv_rn(-d2, no);
        }
        #pragma unroll
        for (int j = 0; j < 4; j++) {
            int sh = 3 - j;
            float m0 = -1e30f, m1 = -1e30f;
            #pragma unroll
            for (int i = 0; i < 16; i++) {
                if ((i >> sh) & 1) m1 = fmaxf(m1, lg[i]);
                else               m0 = fmaxf(m0, lg[i]);
            }
            float s0 = 0.0f, s1 = 0.0f;
            #pragma unroll
            for (int i = 0; i < 16; i++) {
                if ((i >> sh) & 1) s1 = __fadd_rn(s1, expf(__fsub_rn(lg[i], m1)));
                else               s0 = __fadd_rn(s0, expf(__fsub_rn(lg[i], m0)));
            }
            llr_s[4*s + j] = __fsub_rn(__fadd_rn(logf(s0), m0),
                                       __fadd_rn(logf(s1), m1));
        }
    }
    __syncthreads();

    // ---- BP: flooding sum-product, NITER iterations ----
    int   idx[CPT][DVc];
    float c2v[CPT][6];
    #pragma unroll
    for (int c = 0; c < CPT; c++) {
        int m = tid + c * Tthr;
        #pragma unroll
        for (int j = 0; j < DVc; j++) idx[c][j] = a_idx[m * DVc + j];
        #pragma unroll
        for (int j = 0; j < 6; j++) c2v[c][j] = 0.0f;
    }

    for (int it = 0; it <= NITERc; it++) {
        // zero marginals
        for (int n = tid; n < Nc; n += Tthr) vac_s[n] = 0.0f;
        __syncthreads();
        // scatter c2v -> variable marginals
        #pragma unroll
        for (int c = 0; c < CPT; c++) {
            #pragma unroll
            for (int j = 0; j < DVc; j++) atomicAdd(&vac_s[idx[c][j]], c2v[c][j]);
            vac_s[Kc + tid + c * Tthr] = c2v[c][5];   // parity var: single edge
        }
        __syncthreads();
        if (it == NITERc) break;

        // check-node update (each thread owns whole rows)
        #pragma unroll
        for (int c = 0; c < CPT; c++) {
            int m = tid + c * Tthr;
            float lt[6], sg[6];
            float cs = 0.0f, ns = 0.0f;
            #pragma unroll
            for (int j = 0; j < 6; j++) {
                int vn = (j < DVc) ? idx[c][j] : (Kc + m);
                float v2c = __fsub_rn(__fadd_rn(llr_s[vn], vac_s[vn]), c2v[c][j]);
                float av  = fminf(fmaxf(fabsf(v2c), 1e-6f), 20.0f);
                float l   = logf(xla_tanh(__fmul_rn(av, 0.5f)));
                float sgn = (v2c < 0.0f) ? 1.0f : 0.0f;
                lt[j] = l; sg[j] = sgn;
                cs = __fadd_rn(cs, l);
                ns = __fadd_rn(ns, sgn);
            }
            #pragma unroll
            for (int j = 0; j < 6; j++) {
                float ex  = expf(fminf(__fsub_rn(cs, lt[j]), -1e-7f));
                int   par = (int)(__fsub_rn(ns, sg[j]));
                // sp * 2*atanh(ex), atanh = 0.5*(log1p(x)-log1p(-x)) (CHLO decomp);
                // the 2*0.5 cancels exactly in fp32.
                float d   = __fsub_rn(log1pf(ex), log1pf(-ex));
                c2v[c][j] = (par & 1) ? -d : d;
            }
        }
        __syncthreads();
    }

    // ---- outputs: [bits, bits_rx] each [B,K] float ----
    const int* bp = bits + b * Kc;
    for (int k = tid; k < Kc; k += Tthr) {
        float tot = __fadd_rn(llr_s[k], vac_s[k]);
        out[b * Kc + k]            = (float)bp[k];
        out[Bn * Kc + b * Kc + k]  = (tot < 0.0f) ? 1.0f : 0.0f;
    }
}

extern "C" void kernel_launch(void* const* d_in, const int* in_sizes, int n_in,
                              void* d_out, int out_size)
{
    const int*   bits  = (const int*)  d_in[0];
    const int*   a_idx = (const int*)  d_in[1];
    // d_in[2]=edge_cn, d_in[3]=edge_vn: implied by a_idx / row structure, unused
    const float* pre   = (const float*)d_in[4];
    const float* pim   = (const float*)d_in[5];
    const float* nre   = (const float*)d_in[6];
    const float* nim   = (const float*)d_in[7];
    const float* ebno  = (const float*)d_in[8];
    float*       out   = (float*)d_out;

    simplelink_kernel<<<Bn, Tthr>>>(bits, a_idx, pre, pim, nre, nim, ebno, out);
}

// round 3
// speedup vs baseline: 1.9509x; 1.9509x over previous
#include <cuda_runtime.h>

// Problem constants
#define Bn     1024
#define Kc     1056
#define Nc     2112
#define Mc     1056
#define DVc    5
#define NSYMc  528
#define NITERc 20

#define Tthr   352           // threads per block
#define CPT    3             // checks per thread: Mc / Tthr == 3

#define EXCLAMP 0.99999994f  // 1 - 2^-23: value expf(-1e-7) rounds to in fp32

__global__ void __launch_bounds__(Tthr, 2)
simplelink_kernel(const int* __restrict__ bits,
                  const int* __restrict__ a_idx,
                  const float* __restrict__ points_re,
                  const float* __restrict__ points_im,
                  const float* __restrict__ noise_re,
                  const float* __restrict__ noise_im,
                  const float* __restrict__ ebno,
                  float* __restrict__ out)
{
    __shared__ float llr_s[Nc];
    __shared__ float totA[Nc];   // llr + marginals, double-buffered
    __shared__ float totB[Nc];
    __shared__ float pre_s[16], pim_s[16];

    const int b   = blockIdx.x;
    const int tid = threadIdx.x;

    if (tid < 16) { pre_s[tid] = points_re[tid]; pim_s[tid] = points_im[tid]; }

    // ---- load info bits (reuse totA as int staging) ----
    int* cw_s = (int*)totA;
    for (int i = tid; i < Kc; i += Tthr) cw_s[i] = bits[b * Kc + i];
    __syncthreads();

    // ---- LDPC encode: parity_m = XOR of DV info bits ----
    for (int m = tid; m < Mc; m += Tthr) {
        int p = 0;
        #pragma unroll
        for (int j = 0; j < DVc; j++) p += cw_s[a_idx[m * DVc + j]];
        cw_s[Kc + m] = p & 1;
    }
    __syncthreads();

    // ---- noise scaling ----
    const float eb    = ebno[0];
    const float no    = __fdiv_rn(1.0f,
                         __fmul_rn(__fmul_rn(powf(10.0f, __fdiv_rn(eb, 10.0f)), 0.5f), 4.0f));
    const float sigma = sqrtf(__fdiv_rn(no, 2.0f));
    const float inv_no = __fdiv_rn(1.0f, no);

    // ---- QAM map + AWGN + APP demap -> llr ----
    for (int s = tid; s < NSYMc; s += Tthr) {
        int sym = (cw_s[4*s] << 3) | (cw_s[4*s+1] << 2) | (cw_s[4*s+2] << 1) | cw_s[4*s+3];
        float yre = pre_s[sym] + sigma * noise_re[b * NSYMc + s];
        float yim = pim_s[sym] + sigma * noise_im[b * NSYMc + s];
        float lg[16];
        #pragma unroll
        for (int i = 0; i < 16; i++) {
            float dr = yre - pre_s[i];
            float di = yim - pim_s[i];
            lg[i] = -(dr * dr + di * di) * inv_no;
        }
        float llr4[4];
        #pragma unroll
        for (int j = 0; j < 4; j++) {
            int sh = 3 - j;
            float m0 = -1e30f, m1 = -1e30f;
            #pragma unroll
            for (int i = 0; i < 16; i++) {
                if ((i >> sh) & 1) m1 = fmaxf(m1, lg[i]);
                else               m0 = fmaxf(m0, lg[i]);
            }
            float s0 = 0.0f, s1 = 0.0f;
            #pragma unroll
            for (int i = 0; i < 16; i++) {
                float e = __expf(lg[i] - (((i >> sh) & 1) ? m1 : m0));
                if ((i >> sh) & 1) s1 += e;
                else               s0 += e;
            }
            llr4[j] = (__logf(s0) + m0) - (__logf(s1) + m1);
        }
        // llr_s doesn't alias cw_s(totA); safe to write now
        llr_s[4*s+0] = llr4[0]; llr_s[4*s+1] = llr4[1];
        llr_s[4*s+2] = llr4[2]; llr_s[4*s+3] = llr4[3];
    }
    __syncthreads();   // llr_s complete; cw_s (totA) no longer needed

    // ---- BP setup: row indices + register-resident c2v ----
    int   idx[CPT][DVc];
    float c2v[CPT][6];
    #pragma unroll
    for (int c = 0; c < CPT; c++) {
        int m = tid + c * Tthr;
        #pragma unroll
        for (int j = 0; j < DVc; j++) idx[c][j] = a_idx[m * DVc + j];
        #pragma unroll
        for (int j = 0; j < 6; j++) c2v[c][j] = 0.0f;
    }

    // init first buffer with llr (info vars only; parity vars written in scatter)
    for (int n = tid; n < Kc; n += Tthr) totA[n] = llr_s[n];
    __syncthreads();

    float* cur = totA;
    float* nxt = totB;

    for (int it = 0; it <= NITERc; it++) {
        // scatter c2v into cur (pre-initialized with llr); init nxt for next pass
        #pragma unroll
        for (int c = 0; c < CPT; c++) {
            int m = tid + c * Tthr;
            #pragma unroll
            for (int j = 0; j < DVc; j++) atomicAdd(&cur[idx[c][j]], c2v[c][j]);
            cur[Kc + m] = llr_s[Kc + m] + c2v[c][5];   // parity var: single edge
        }
        if (it < NITERc)
            for (int n = tid; n < Kc; n += Tthr) nxt[n] = llr_s[n];
        __syncthreads();
        if (it == NITERc) break;

        // check-node update (each thread owns whole rows)
        #pragma unroll
        for (int c = 0; c < CPT; c++) {
            int m = tid + c * Tthr;
            float lt[6];
            float cs = 0.0f;
            int   signs = 0;
            #pragma unroll
            for (int j = 0; j < 6; j++) {
                int vn = (j < DVc) ? idx[c][j] : (Kc + m);
                float v2c = cur[vn] - c2v[c][j];
                signs |= (v2c < 0.0f) ? (1 << j) : 0;
                float av = fminf(fmaxf(fabsf(v2c), 1e-6f), 20.0f);
                float t  = fminf(__expf(-av), EXCLAMP);
                float l  = __logf(__fdividef(1.0f - t, 1.0f + t));  // log tanh(av/2)
                lt[j] = l;
                cs += l;
            }
            int totpar = __popc(signs);
            #pragma unroll
            for (int j = 0; j < 6; j++) {
                float w  = fminf(cs - lt[j], -1e-7f);
                float ex = fminf(__expf(w), EXCLAMP);
                float d  = __logf(__fdividef(1.0f + ex, 1.0f - ex));  // 2*atanh(ex)
                int par  = (totpar - ((signs >> j) & 1)) & 1;
                c2v[c][j] = par ? -d : d;
            }
        }
        __syncthreads();

        float* tmp = cur; cur = nxt; nxt = tmp;
    }

    // ---- outputs: [bits, bits_rx] each [B,K] float ----
    const int* bp = bits + b * Kc;
    for (int k = tid; k < Kc; k += Tthr) {
        out[b * Kc + k]           = (float)bp[k];
        out[Bn * Kc + b * Kc + k] = (cur[k] < 0.0f) ? 1.0f : 0.0f;
    }
}

extern "C" void kernel_launch(void* const* d_in, const int* in_sizes, int n_in,
                              void* d_out, int out_size)
{
    const int*   bits  = (const int*)  d_in[0];
    const int*   a_idx = (const int*)  d_in[1];
    const float* pre   = (const float*)d_in[4];
    const float* pim   = (const float*)d_in[5];
    const float* nre   = (const float*)d_in[6];
    const float* nim   = (const float*)d_in[7];
    const float* ebno  = (const float*)d_in[8];
    float*       out   = (float*)d_out;

    simplelink_kernel<<<Bn, Tthr>>>(bits, a_idx, pre, pim, nre, nim, ebno, out);
}

// round 6
// speedup vs baseline: 2.3270x; 1.1928x over previous
#include <cuda_runtime.h>

// Problem constants
#define Bn     1024
#define Kc     1056
#define Nc     2112
#define Mc     1056
#define DVc    5
#define NSYMc  528
#define NITERc 20

#define Tthr   352           // threads per block
#define CPT    3             // checks per thread: Mc / Tthr == 3

#define EXCLAMP 0.99999994f  // ~ fp32 rounding of exp(-1e-7): reference saturation

__global__ void __launch_bounds__(Tthr, 2)
simplelink_kernel(const int* __restrict__ bits,
                  const int* __restrict__ a_idx,
                  const float* __restrict__ points_re,
                  const float* __restrict__ points_im,
                  const float* __restrict__ noise_re,
                  const float* __restrict__ noise_im,
                  const float* __restrict__ ebno,
                  float* __restrict__ out)
{
    __shared__ float llr_s[Nc];
    __shared__ float totA[Nc];   // llr + marginals, double-buffered
    __shared__ float totB[Nc];
    __shared__ float pre_s[16], pim_s[16];

    const int b   = blockIdx.x;
    const int tid = threadIdx.x;

    if (tid < 16) { pre_s[tid] = points_re[tid]; pim_s[tid] = points_im[tid]; }

    // ---- load info bits (reuse totA as int staging) ----
    int* cw_s = (int*)totA;
    for (int i = tid; i < Kc; i += Tthr) cw_s[i] = bits[b * Kc + i];
    __syncthreads();

    // ---- LDPC encode: parity_m = XOR of DV info bits ----
    for (int m = tid; m < Mc; m += Tthr) {
        int p = 0;
        #pragma unroll
        for (int j = 0; j < DVc; j++) p += cw_s[a_idx[m * DVc + j]];
        cw_s[Kc + m] = p & 1;
    }
    __syncthreads();

    // ---- noise scaling ----
    const float eb    = ebno[0];
    const float no    = __fdiv_rn(1.0f,
                         __fmul_rn(__fmul_rn(powf(10.0f, __fdiv_rn(eb, 10.0f)), 0.5f), 4.0f));
    const float sigma = sqrtf(__fdiv_rn(no, 2.0f));
    const float inv_no = __fdiv_rn(1.0f, no);

    // ---- QAM map + AWGN + APP demap -> llr ----
    for (int s = tid; s < NSYMc; s += Tthr) {
        int sym = (cw_s[4*s] << 3) | (cw_s[4*s+1] << 2) | (cw_s[4*s+2] << 1) | cw_s[4*s+3];
        float yre = pre_s[sym] + sigma * noise_re[b * NSYMc + s];
        float yim = pim_s[sym] + sigma * noise_im[b * NSYMc + s];
        float lg[16];
        #pragma unroll
        for (int i = 0; i < 16; i++) {
            float dr = yre - pre_s[i];
            float di = yim - pim_s[i];
            lg[i] = -(dr * dr + di * di) * inv_no;
        }
        float llr4[4];
        #pragma unroll
        for (int j = 0; j < 4; j++) {
            int sh = 3 - j;
            float m0 = -1e30f, m1 = -1e30f;
            #pragma unroll
            for (int i = 0; i < 16; i++) {
                if ((i >> sh) & 1) m1 = fmaxf(m1, lg[i]);
                else               m0 = fmaxf(m0, lg[i]);
            }
            float s0 = 0.0f, s1 = 0.0f;
            #pragma unroll
            for (int i = 0; i < 16; i++) {
                float e = __expf(lg[i] - (((i >> sh) & 1) ? m1 : m0));
                if ((i >> sh) & 1) s1 += e;
                else               s0 += e;
            }
            llr4[j] = (__logf(s0) + m0) - (__logf(s1) + m1);
        }
        llr_s[4*s+0] = llr4[0]; llr_s[4*s+1] = llr4[1];
        llr_s[4*s+2] = llr4[2]; llr_s[4*s+3] = llr4[3];
    }
    __syncthreads();   // llr_s complete; cw_s (totA) dead

    // ---- BP setup ----
    int   idx[CPT][DVc];
    float c2v[CPT][DVc];
    float pn5[CPT], pd5[CPT];   // parity-edge tanh factors (constant over iters)
    int   psgn[CPT];
    float llr_r[CPT];           // this thread's info-var llr values (for nxt init)

    #pragma unroll
    for (int c = 0; c < CPT; c++) {
        int m = tid + c * Tthr;
        #pragma unroll
        for (int j = 0; j < DVc; j++) idx[c][j] = a_idx[m * DVc + j];
        #pragma unroll
        for (int j = 0; j < DVc; j++) c2v[c][j] = 0.0f;
        // parity edge: v2c is llr_parity forever (degree-1 var, message cancels)
        float lp  = llr_s[Kc + m];
        float avp = fminf(fmaxf(fabsf(lp), 1e-6f), 20.0f);
        float ep  = __expf(-avp);
        pn5[c] = 1.0f - ep;
        pd5[c] = 1.0f + ep;
        psgn[c] = (lp < 0.0f) ? 1 : 0;
        llr_r[c] = llr_s[tid + c * Tthr];
    }

    // init first marginal buffer with llr (info vars only)
    #pragma unroll
    for (int c = 0; c < CPT; c++) totA[tid + c * Tthr] = llr_r[c];
    __syncthreads();

    float* cur = totA;
    float* nxt = totB;

    for (int it = 0; it <= NITERc; it++) {
        // scatter c2v into cur (pre-initialized with llr); prep nxt
        #pragma unroll
        for (int c = 0; c < CPT; c++) {
            #pragma unroll
            for (int j = 0; j < DVc; j++) atomicAdd(&cur[idx[c][j]], c2v[c][j]);
        }
        if (it < NITERc) {
            #pragma unroll
            for (int c = 0; c < CPT; c++) nxt[tid + c * Tthr] = llr_r[c];
        }
        __syncthreads();
        if (it == NITERc) break;

        // check-node update (each thread owns whole rows)
        #pragma unroll
        for (int c = 0; c < CPT; c++) {
            float n[DVc], dd[DVc];
            int signs = psgn[c] << DVc;
            #pragma unroll
            for (int j = 0; j < DVc; j++) {
                float v2c = cur[idx[c][j]] - c2v[c][j];
                signs |= ((v2c < 0.0f) ? 1 : 0) << j;
                float av = fminf(fmaxf(fabsf(v2c), 1e-6f), 20.0f);
                float e  = __expf(-av);
                n[j]  = 1.0f - e;
                dd[j] = 1.0f + e;
            }
            int totpar = __popc(signs);
            // suffix products seeded with the parity-edge constants
            float sN[DVc], sD[DVc];
            float suN = pn5[c], suD = pd5[c];
            #pragma unroll
            for (int j = DVc - 1; j >= 0; j--) {
                sN[j] = suN; sD[j] = suD;
                suN *= n[j]; suD *= dd[j];
            }
            float prN = 1.0f, prD = 1.0f;
            #pragma unroll
            for (int j = 0; j < DVc; j++) {
                float Pn = prN * sN[j];
                float Pd = prD * sD[j];
                Pn = fminf(Pn, EXCLAMP * Pd);
                float dv = __logf(__fdividef(Pd + Pn, Pd - Pn));  // 2*atanh(Pn/Pd)
                int par = (totpar - ((signs >> j) & 1)) & 1;
                c2v[c][j] = par ? -dv : dv;
                prN *= n[j]; prD *= dd[j];
            }
        }
        __syncthreads();

        float* tmp = cur; cur = nxt; nxt = tmp;
    }

    // ---- outputs: [bits, bits_rx] each [B,K] float ----
    const int* bp = bits + b * Kc;
    for (int k = tid; k < Kc; k += Tthr) {
        out[b * Kc + k]           = (float)bp[k];
        out[Bn * Kc + b * Kc + k] = (cur[k] < 0.0f) ? 1.0f : 0.0f;
    }
}

extern "C" void kernel_launch(void* const* d_in, const int* in_sizes, int n_in,
                              void* d_out, int out_size)
{
    const int*   bits  = (const int*)  d_in[0];
    const int*   a_idx = (const int*)  d_in[1];
    const float* pre   = (const float*)d_in[4];
    const float* pim   = (const float*)d_in[5];
    const float* nre   = (const float*)d_in[6];
    const float* nim   = (const float*)d_in[7];
    const float* ebno  = (const float*)d_in[8];
    float*       out   = (float*)d_out;

    simplelink_kernel<<<Bn, Tthr>>>(bits, a_idx, pre, pim, nre, nim, ebno, out);
}